// round 4
// baseline (speedup 1.0000x reference)
#include <cuda_runtime.h>

#define LLEN 1024
#define NB   64

// ---- device scratch (no allocations allowed) ----
__device__ float g_cat [NB * 192 * LLEN];
__device__ float g_dec [NB * 192 * LLEN];
__device__ float g_encU[NB * 64  * LLEN];
__device__ int   g_ids [NB];

// ------------------------------------------------------------------
__global__ void ids_kernel(const float* __restrict__ x) {
    int b = threadIdx.x;
    if (b < NB) g_ids[b] = (int)x[(long)b * (LLEN + 1) + LLEN];
}

// ------------------------------------------------------------------
// Fused block: y = relu(W2 @ relu(dilated_conv5(x, W1) + b1) + b2)
// conv1: CIN -> 128 (k=5, dilation DIL), conv2: 128 -> 32 (1x1)
// 512 threads = 16 warps = 8 co-groups x 2 l-groups. Two co-halves of 64.
// Each warp: 8 output channels x (TIL/2) l-positions. 2 CTAs/SM.
// smem: xs[CIN][XW] | ws1[CCH][5][64] | hs[64][TIL] | ws2[128][32] | b1s | b2s
// ------------------------------------------------------------------
template<int CIN, int DIL, int TIL>
__global__ void __launch_bounds__(512, 2)
block_kernel(const float* __restrict__ xin, long in_samp_stride, int in_ch_stride,
             const float* __restrict__ w1, const float* __restrict__ b1,
             const float* __restrict__ w2, const float* __restrict__ b2,
             float* __restrict__ yout, long out_samp_stride,
             const int* __restrict__ ids,
             long w1_cs, long b1_cs, long w2_cs, long b2_cs)
{
    constexpr int XW  = TIL + 4 * DIL;           // input tile incl. halo
    constexpr int CCH = (CIN < 8) ? CIN : 8;     // staged input-channel chunk
    constexpr int LH  = TIL / 2;                 // l per l-group
    constexpr int NI  = LH / 32;                 // l sub-iters per thread
    extern __shared__ float sm[];
    float* xs  = sm;                             // CIN * XW
    float* ws1 = xs  + CIN * XW;                 // CCH * 5 * 64   [cil][t][co]
    float* hs  = ws1 + CCH * 320;                // 64 * TIL
    float* ws2 = hs  + 64 * TIL;                 // 128 * 32       [k][co2]
    float* b1s = ws2 + 128 * 32;                 // 128
    float* b2s = b1s + 128;                      // 32

    const int b    = blockIdx.y;
    const int l0   = blockIdx.x * TIL;
    const int tid  = threadIdx.x;
    const int warp = tid >> 5;
    const int ln   = tid & 31;
    const int wg   = warp >> 3;                  // l-group (0..1)
    const int wc   = warp & 7;                   // co-group (0..7)
    const int lb   = wg * LH + ln;               // lane's base l within tile

    const float* w1p = w1;
    const float* b1p = b1;
    const float* w2p = w2;
    const float* b2p = b2;
    if (ids) {
        int c = ids[b];
        w1p += (long)c * w1_cs;  b1p += (long)c * b1_cs;
        w2p += (long)c * w2_cs;  b2p += (long)c * b2_cs;
    }

    // ---- stage input tile (halo 2*DIL each side, zero-padded) ----
    const float* xb = xin + (long)b * in_samp_stride;
    for (int i = tid; i < CIN * XW; i += 512) {
        int ci = i / XW, j = i - ci * XW;
        int pos = l0 - 2 * DIL + j;
        xs[i] = (pos >= 0 && pos < LLEN) ? xb[(long)ci * in_ch_stride + pos] : 0.f;
    }
    if (tid < 128) b1s[tid] = b1p[tid];
    if (tid < 32)  b2s[tid] = b2p[tid];
    // ws2: [k][co2]; consecutive tid -> consecutive smem
    for (int i = tid; i < 32 * 128; i += 512) {
        int co = i & 31, k = i >> 5;
        ws2[k * 32 + co] = w2p[co * 128 + k];
    }

    // conv2 accumulators persist across halves: warp owns co2 = wc*4 .. +4
    float a2[4][NI];
    #pragma unroll
    for (int c = 0; c < 4; c++)
        #pragma unroll
        for (int i = 0; i < NI; i++) a2[c][i] = 0.f;

    #pragma unroll
    for (int half = 0; half < 2; half++) {
        const int coB = half * 64;

        // ---- conv1: warp owns co = coB + wc*8 .. +8, l = lb + 32*i ----
        float acc[8][NI];
        #pragma unroll
        for (int c = 0; c < 8; c++)
            #pragma unroll
            for (int i = 0; i < NI; i++) acc[c][i] = 0.f;

        for (int ci0 = 0; ci0 < CIN; ci0 += CCH) {
            __syncthreads();   // orders prev conv2/hs reads vs ws1 restage
            for (int i = tid; i < CCH * 320; i += 512) {
                int cil = i / 320;
                int r   = i - cil * 320;
                int t   = r >> 6;
                int co  = r & 63;
                ws1[i] = w1p[(long)(coB + co) * (CIN * 5) + (ci0 + cil) * 5 + t];
            }
            __syncthreads();
            #pragma unroll
            for (int cil = 0; cil < CCH; cil++) {
                const float* xrow  = xs + (ci0 + cil) * XW + lb;
                const float* wbase = ws1 + cil * 320 + wc * 8;
                #pragma unroll
                for (int t = 0; t < 5; t++) {
                    float4 wA = *(const float4*)(wbase + t * 64);       // bcast
                    float4 wB = *(const float4*)(wbase + t * 64 + 4);   // bcast
                    float xv[NI];
                    #pragma unroll
                    for (int i = 0; i < NI; i++) xv[i] = xrow[32 * i + t * DIL];
                    #pragma unroll
                    for (int i = 0; i < NI; i++) {
                        acc[0][i] = fmaf(wA.x, xv[i], acc[0][i]);
                        acc[1][i] = fmaf(wA.y, xv[i], acc[1][i]);
                        acc[2][i] = fmaf(wA.z, xv[i], acc[2][i]);
                        acc[3][i] = fmaf(wA.w, xv[i], acc[3][i]);
                        acc[4][i] = fmaf(wB.x, xv[i], acc[4][i]);
                        acc[5][i] = fmaf(wB.y, xv[i], acc[5][i]);
                        acc[6][i] = fmaf(wB.z, xv[i], acc[6][i]);
                        acc[7][i] = fmaf(wB.w, xv[i], acc[7][i]);
                    }
                }
            }
        }
        __syncthreads();
        // ---- bias + relu -> hs (co local to half) ----
        #pragma unroll
        for (int c = 0; c < 8; c++) {
            int co = wc * 8 + c;
            float bb = b1s[coB + co];
            #pragma unroll
            for (int i = 0; i < NI; i++) {
                float v = acc[c][i] + bb;
                hs[co * TIL + lb + 32 * i] = v > 0.f ? v : 0.f;
            }
        }
        __syncthreads();

        // ---- conv2 partial (k over this half) ----
        #pragma unroll 4
        for (int k = 0; k < 64; k++) {
            float4 w4 = *(const float4*)(ws2 + (coB + k) * 32 + wc * 4);  // bcast
            #pragma unroll
            for (int i = 0; i < NI; i++) {
                float xv = hs[k * TIL + lb + 32 * i];
                a2[0][i] = fmaf(w4.x, xv, a2[0][i]);
                a2[1][i] = fmaf(w4.y, xv, a2[1][i]);
                a2[2][i] = fmaf(w4.z, xv, a2[2][i]);
                a2[3][i] = fmaf(w4.w, xv, a2[3][i]);
            }
        }
    }

    float* yb = yout + (long)b * out_samp_stride;
    #pragma unroll
    for (int c = 0; c < 4; c++) {
        int co2 = wc * 4 + c;
        float bb = b2s[co2];
        #pragma unroll
        for (int i = 0; i < NI; i++) {
            float v = a2[c][i] + bb;
            yb[(long)co2 * LLEN + l0 + lb + 32 * i] = v > 0.f ? v : 0.f;
        }
    }
}

// ------------------------------------------------------------------
// compress conv (192 -> 64, 1x1) fused with avgpool(2)+repeat(2)
// CTILE 64, 512 threads, 2 CTA/SM. warp = 8 co x 32 l.
// ------------------------------------------------------------------
#define CTILE 64
__global__ void __launch_bounds__(512, 2)
comp_kernel(const float* __restrict__ cat, const float* __restrict__ cw,
            const float* __restrict__ cb, float* __restrict__ out)
{
    extern __shared__ float sm[];
    float* xs  = sm;                   // 192 * 64
    float* ws  = xs + 192 * CTILE;     // 192 * 64   [k][co]
    float* cbs = ws + 192 * 64;        // 64

    const int b    = blockIdx.y;
    const int l0   = blockIdx.x * CTILE;
    const int tid  = threadIdx.x;
    const int warp = tid >> 5;
    const int ln   = tid & 31;
    const int wg   = warp >> 3;        // l-group (0..1)
    const int wc   = warp & 7;         // co-group (0..7)
    const int lb   = wg * 32 + ln;

    const float* catb = cat + (long)b * 192 * LLEN;
    for (int i = tid; i < 192 * CTILE; i += 512) {
        int ch = i / CTILE, j = i - ch * CTILE;
        xs[i] = catb[(long)ch * LLEN + l0 + j];
    }
    for (int i = tid; i < 64 * 192; i += 512) {
        int co = i & 63, k = i >> 6;
        ws[k * 64 + co] = cw[co * 192 + k];
    }
    if (tid < 64) cbs[tid] = cb[tid];
    __syncthreads();

    float acc[8];
    #pragma unroll
    for (int c = 0; c < 8; c++) acc[c] = 0.f;

    #pragma unroll 4
    for (int k = 0; k < 192; k++) {
        float4 wA = *(const float4*)(ws + k * 64 + wc * 8);       // bcast
        float4 wB = *(const float4*)(ws + k * 64 + wc * 8 + 4);   // bcast
        float xv = xs[k * CTILE + lb];
        acc[0] = fmaf(wA.x, xv, acc[0]);
        acc[1] = fmaf(wA.y, xv, acc[1]);
        acc[2] = fmaf(wA.z, xv, acc[2]);
        acc[3] = fmaf(wA.w, xv, acc[3]);
        acc[4] = fmaf(wB.x, xv, acc[4]);
        acc[5] = fmaf(wB.y, xv, acc[5]);
        acc[6] = fmaf(wB.z, xv, acc[6]);
        acc[7] = fmaf(wB.w, xv, acc[7]);
    }

    float* ob = out + (long)b * 64 * LLEN;
    #pragma unroll
    for (int c = 0; c < 8; c++) {
        int co = wc * 8 + c;
        float v = acc[c] + cbs[co];
        // avgpool(2)+nearest upsample(2): adjacent lanes hold the l pair
        float p = __shfl_xor_sync(0xffffffffu, v, 1);
        ob[(long)co * LLEN + l0 + lb] = 0.5f * (v + p);
    }
}

// ------------------------------------------------------------------
// final per-sample 1x1 conv: 192 -> 1, weights selected by combination id
// ------------------------------------------------------------------
__global__ void __launch_bounds__(256, 1)
final_kernel(const float* __restrict__ dec, const float* __restrict__ cw,
             const float* __restrict__ cbv, float* __restrict__ out)
{
    __shared__ float ws[192];
    const int b   = blockIdx.x;
    const int tid = threadIdx.x;
    const int c   = g_ids[b];
    if (tid < 192) ws[tid] = cw[(long)c * 192 + tid];
    __syncthreads();
    const float bb = cbv[c];
    const float* db = dec + (long)b * 192 * LLEN;
    for (int l = tid; l < LLEN; l += 256) {
        float s = bb;
        #pragma unroll 8
        for (int ch = 0; ch < 192; ch++) s = fmaf(ws[ch], db[(long)ch * LLEN + l], s);
        out[(long)b * LLEN + l] = s;
    }
}

// ------------------------------------------------------------------
static constexpr int smem_block(int cin, int dil, int til) {
    int xw  = til + 4 * dil;
    int cch = cin < 8 ? cin : 8;
    return (cin * xw + cch * 320 + 64 * til + 128 * 32 + 160) * 4;
}
static constexpr int SMEM_C = (192 * CTILE + 192 * 64 + 64) * 4;

template<int CIN, int DIL, int TIL>
static void launch_block(const float* xin, long iss, int ics,
                         const float* w1, const float* b1,
                         const float* w2, const float* b2,
                         float* yout, long oss,
                         const int* ids, long w1cs, long b1cs, long w2cs, long b2cs)
{
    static bool attr_done = false;
    if (!attr_done) {
        cudaFuncSetAttribute(block_kernel<CIN, DIL, TIL>,
                             cudaFuncAttributeMaxDynamicSharedMemorySize,
                             smem_block(CIN, DIL, TIL));
        attr_done = true;
    }
    dim3 grid(LLEN / TIL, NB);
    block_kernel<CIN, DIL, TIL><<<grid, 512, smem_block(CIN, DIL, TIL)>>>(
        xin, iss, ics, w1, b1, w2, b2, yout, oss, ids, w1cs, b1cs, w2cs, b2cs);
}

extern "C" void kernel_launch(void* const* d_in, const int* in_sizes, int n_in,
                              void* d_out, int out_size)
{
    const float* x        = (const float*)d_in[0];
    const float* enc0_w1  = (const float*)d_in[1];
    const float* enc0_b1  = (const float*)d_in[2];
    const float* enc0_w2  = (const float*)d_in[3];
    const float* enc0_b2  = (const float*)d_in[4];
    const float* enc_w1   = (const float*)d_in[5];
    const float* enc_b1   = (const float*)d_in[6];
    const float* enc_w2   = (const float*)d_in[7];
    const float* enc_b2   = (const float*)d_in[8];
    const float* comp_w   = (const float*)d_in[9];
    const float* comp_b   = (const float*)d_in[10];
    const float* decf0_w1 = (const float*)d_in[11];
    const float* decf0_b1 = (const float*)d_in[12];
    const float* decf0_w2 = (const float*)d_in[13];
    const float* decf0_b2 = (const float*)d_in[14];
    const float* decf_w1  = (const float*)d_in[15];
    const float* decf_b1  = (const float*)d_in[16];
    const float* decf_w2  = (const float*)d_in[17];
    const float* decf_b2  = (const float*)d_in[18];
    const float* decv_w1  = (const float*)d_in[19];
    const float* decv_b1  = (const float*)d_in[20];
    const float* decv_w2  = (const float*)d_in[21];
    const float* decv_b2  = (const float*)d_in[22];
    const float* decv_cw  = (const float*)d_in[23];
    const float* decv_cb  = (const float*)d_in[24];
    float* out = (float*)d_out;

    float *cat, *dec, *encU;
    int* idsp;
    cudaGetSymbolAddress((void**)&cat,  g_cat);
    cudaGetSymbolAddress((void**)&dec,  g_dec);
    cudaGetSymbolAddress((void**)&encU, g_encU);
    cudaGetSymbolAddress((void**)&idsp, g_ids);

    cudaFuncSetAttribute(comp_kernel, cudaFuncAttributeMaxDynamicSharedMemorySize, SMEM_C);

    const long SS = (long)192 * LLEN;

    ids_kernel<<<1, 64>>>(x);

    // ---- encoder ----
    launch_block<1, 1, 128>(x, (long)(LLEN + 1), 0,
                            enc0_w1, enc0_b1, enc0_w2, enc0_b2,
                            cat, SS, nullptr, 0, 0, 0, 0);
    launch_block<32, 2, 128>(cat + 0 * 32 * LLEN, SS, LLEN,
                             enc_w1 + 0 * 20480, enc_b1 + 0 * 128, enc_w2 + 0 * 4096, enc_b2 + 0 * 32,
                             cat + 1 * 32 * LLEN, SS, nullptr, 0, 0, 0, 0);
    launch_block<32, 4, 128>(cat + 1 * 32 * LLEN, SS, LLEN,
                             enc_w1 + 1 * 20480, enc_b1 + 1 * 128, enc_w2 + 1 * 4096, enc_b2 + 1 * 32,
                             cat + 2 * 32 * LLEN, SS, nullptr, 0, 0, 0, 0);
    launch_block<32, 8, 128>(cat + 2 * 32 * LLEN, SS, LLEN,
                             enc_w1 + 2 * 20480, enc_b1 + 2 * 128, enc_w2 + 2 * 4096, enc_b2 + 2 * 32,
                             cat + 3 * 32 * LLEN, SS, nullptr, 0, 0, 0, 0);
    launch_block<32, 16, 128>(cat + 3 * 32 * LLEN, SS, LLEN,
                              enc_w1 + 3 * 20480, enc_b1 + 3 * 128, enc_w2 + 3 * 4096, enc_b2 + 3 * 32,
                              cat + 4 * 32 * LLEN, SS, nullptr, 0, 0, 0, 0);
    launch_block<32, 32, 128>(cat + 4 * 32 * LLEN, SS, LLEN,
                              enc_w1 + 4 * 20480, enc_b1 + 4 * 128, enc_w2 + 4 * 4096, enc_b2 + 4 * 32,
                              cat + 5 * 32 * LLEN, SS, nullptr, 0, 0, 0, 0);

    // ---- compress + pool + upsample ----
    {
        dim3 grid(LLEN / CTILE, NB);
        comp_kernel<<<grid, 512, SMEM_C>>>(cat, comp_w, comp_b, encU);
    }

    // ---- fixed decoder ----
    launch_block<64, 32, 64>(encU, (long)64 * LLEN, LLEN,
                             decf0_w1, decf0_b1, decf0_w2, decf0_b2,
                             dec, SS, nullptr, 0, 0, 0, 0);
    launch_block<32, 16, 128>(dec + 0 * 32 * LLEN, SS, LLEN,
                              decf_w1 + 0 * 20480, decf_b1 + 0 * 128, decf_w2 + 0 * 4096, decf_b2 + 0 * 32,
                              dec + 1 * 32 * LLEN, SS, nullptr, 0, 0, 0, 0);
    launch_block<32, 8, 128>(dec + 1 * 32 * LLEN, SS, LLEN,
                             decf_w1 + 1 * 20480, decf_b1 + 1 * 128, decf_w2 + 1 * 4096, decf_b2 + 1 * 32,
                             dec + 2 * 32 * LLEN, SS, nullptr, 0, 0, 0, 0);
    launch_block<32, 4, 128>(dec + 2 * 32 * LLEN, SS, LLEN,
                             decf_w1 + 2 * 20480, decf_b1 + 2 * 128, decf_w2 + 2 * 4096, decf_b2 + 2 * 32,
                             dec + 3 * 32 * LLEN, SS, nullptr, 0, 0, 0, 0);

    // ---- variable decoder: only the per-sample selected combination ----
    launch_block<32, 2, 128>(dec + 3 * 32 * LLEN, SS, LLEN,
                             decv_w1 + 0 * 20480, decv_b1 + 0 * 128, decv_w2 + 0 * 4096, decv_b2 + 0 * 32,
                             dec + 4 * 32 * LLEN, SS,
                             idsp, 40960, 256, 8192, 64);
    launch_block<32, 1, 128>(dec + 4 * 32 * LLEN, SS, LLEN,
                             decv_w1 + 1 * 20480, decv_b1 + 1 * 128, decv_w2 + 1 * 4096, decv_b2 + 1 * 32,
                             dec + 5 * 32 * LLEN, SS,
                             idsp, 40960, 256, 8192, 64);

    // ---- final 1x1 conv (per-sample weights) ----
    final_kernel<<<NB, 256>>>(dec, decv_cw, decv_cb, out);
}

// round 5
// speedup vs baseline: 2.1568x; 2.1568x over previous
#include <cuda_runtime.h>
#include <cuda_bf16.h>

#define LLEN 1024
#define NB   64

// ---- device scratch (no allocations allowed) ----
__device__ float g_cat [NB * 192 * LLEN];
__device__ float g_dec [NB * 192 * LLEN];
__device__ float g_encU[NB * 64  * LLEN];
__device__ int   g_ids [NB];

// ------------------------------------------------------------------
__global__ void ids_kernel(const float* __restrict__ x) {
    int b = threadIdx.x;
    if (b < NB) g_ids[b] = (int)x[(long)b * (LLEN + 1) + LLEN];
}

// ------------------------------------------------------------------
__device__ __forceinline__ void mma_bf16(float* c, const unsigned* a,
                                         unsigned b0, unsigned b1) {
    asm volatile(
        "mma.sync.aligned.m16n8k16.row.col.f32.bf16.bf16.f32 "
        "{%0,%1,%2,%3}, {%4,%5,%6,%7}, {%8,%9}, {%0,%1,%2,%3};\n"
        : "+f"(c[0]), "+f"(c[1]), "+f"(c[2]), "+f"(c[3])
        : "r"(a[0]), "r"(a[1]), "r"(a[2]), "r"(a[3]), "r"(b0), "r"(b1));
}

__device__ __forceinline__ void split_bf16(float v, __nv_bfloat16& hi, __nv_bfloat16& lo) {
    hi = __float2bfloat16(v);
    lo = __float2bfloat16(v - __bfloat162float(hi));
}

// ------------------------------------------------------------------
// Fused TCN block via tensor cores (bf16x2 split, fp32 accum):
//   conv1: CIN -> 128 (k=5, dilation DIL) + bias + relu
//   conv2: 128 -> 32 (1x1) + bias + relu
// One CTA = [co all] x [l tile of 128]. 512 threads = 16 warps.
// conv1 warps: 4m x 4n grid, each m32 x n32 (2 m-tiles x 4 n-tiles of m16n8k16).
// K-dim = ci (chunks of 16), t looped outside (compile-time DIL offsets).
// conv2 warps: 2m x 8n, each m16 x n16.
// smem (bf16 pairs stored as hi/lo planes, row stride padded to !=bank-cycle):
//   xt[XW][CINP]   x transposed (l-major, ci contiguous)  hi+lo
//   wa[128][CINP]  W1 for current t (co-major, ci contig)  hi+lo
//   hT[128l][128co] conv1 output transposed (l-major)      hi+lo
//   w2[32][128]    W2 (co2-major, k contig)                hi+lo
// ------------------------------------------------------------------
template<int CIN, int DIL>
__global__ void __launch_bounds__(512, 1)
block_mma_kernel(const float* __restrict__ xin, long iss, int ics,
                 const float* __restrict__ w1, const float* __restrict__ b1,
                 const float* __restrict__ w2, const float* __restrict__ b2,
                 float* __restrict__ yout, long oss,
                 const int* __restrict__ ids,
                 long w1_cs, long b1_cs, long w2_cs, long b2_cs)
{
    constexpr int TIL  = 128;
    constexpr int CINP = (CIN < 16) ? 16 : CIN;      // padded K per t
    constexpr int NK   = CINP / 16;                  // k16 steps per t
    constexpr int XW   = TIL + 4 * DIL;              // staged x width incl halo
    constexpr int RWB  = CINP / 2 + 4;               // xt row stride (words)
    constexpr int RWA  = CINP / 2 + 4;               // wa row stride (words)
    constexpr int RWH  = 68;                         // hT row stride (words)
    constexpr int RW2  = 68;                         // w2 row stride (words)

    extern __shared__ unsigned smw[];
    unsigned* xtH = smw;
    unsigned* xtL = xtH + XW * RWB;
    unsigned* waH = xtL + XW * RWB;
    unsigned* waL = waH + 128 * RWA;
    unsigned* hH  = waL + 128 * RWA;
    unsigned* hL  = hH  + TIL * RWH;
    unsigned* w2H = hL  + TIL * RWH;
    unsigned* w2L = w2H + 32 * RW2;
    float*    b1s = (float*)(w2L + 32 * RW2);        // 128
    float*    b2s = b1s + 128;                       // 32

    __nv_bfloat16* xtHb = (__nv_bfloat16*)xtH;
    __nv_bfloat16* xtLb = (__nv_bfloat16*)xtL;
    __nv_bfloat16* waHb = (__nv_bfloat16*)waH;
    __nv_bfloat16* waLb = (__nv_bfloat16*)waL;
    __nv_bfloat16* hHb  = (__nv_bfloat16*)hH;
    __nv_bfloat16* hLb  = (__nv_bfloat16*)hL;
    __nv_bfloat16* w2Hb = (__nv_bfloat16*)w2H;
    __nv_bfloat16* w2Lb = (__nv_bfloat16*)w2L;

    const int b    = blockIdx.y;
    const int l0   = blockIdx.x * TIL;
    const int tid  = threadIdx.x;
    const int warp = tid >> 5;
    const int ln   = tid & 31;
    const int lq   = ln & 3;        // lane % 4 (k / col quad)
    const int lg   = ln >> 2;       // lane / 4 (row group)

    const float* w1p = w1;
    const float* b1p = b1;
    const float* w2p = w2;
    const float* b2p = b2;
    if (ids) {
        int c = ids[b];
        w1p += (long)c * w1_cs;  b1p += (long)c * b1_cs;
        w2p += (long)c * w2_cs;  b2p += (long)c * b2_cs;
    }

    // ---- stage x (transposed, split) ----
    const float* xb = xin + (long)b * iss;
    for (int ci = warp; ci < CINP; ci += 16) {
        for (int r = ln; r < XW; r += 32) {
            int pos = l0 - 2 * DIL + r;
            float v = (ci < CIN && pos >= 0 && pos < LLEN)
                      ? xb[(long)ci * ics + pos] : 0.f;
            __nv_bfloat16 hv, lv; split_bf16(v, hv, lv);
            xtHb[r * (RWB * 2) + ci] = hv;
            xtLb[r * (RWB * 2) + ci] = lv;
        }
    }
    // ---- stage W2 (split) + biases ----
    for (int i = tid; i < 32 * 128; i += 512) {
        int co = i >> 7, k = i & 127;
        __nv_bfloat16 hv, lv; split_bf16(w2p[i], hv, lv);
        w2Hb[co * (RW2 * 2) + k] = hv;
        w2Lb[co * (RW2 * 2) + k] = lv;
    }
    if (tid < 128) b1s[tid] = b1p[tid];
    if (tid < 32)  b2s[tid] = b2p[tid];

    // ---- conv1 mainloop ----
    const int wm = warp >> 2;     // 0..3 (m group of 32 co)
    const int wn = warp & 3;      // 0..3 (n group of 32 l)
    float acc[2][4][4];
    #pragma unroll
    for (int mt = 0; mt < 2; mt++)
        #pragma unroll
        for (int nt = 0; nt < 4; nt++)
            #pragma unroll
            for (int q = 0; q < 4; q++) acc[mt][nt][q] = 0.f;

    #pragma unroll
    for (int t = 0; t < 5; t++) {
        __syncthreads();   // prev-t mma done (first time: x staging done)
        // stage W1(:, :, t) split, layout [co][ci]
        for (int i = tid; i < 128 * CINP; i += 512) {
            int co = i / CINP, ci = i % CINP;
            float v = (ci < CIN) ? w1p[(long)co * (CIN * 5) + ci * 5 + t] : 0.f;
            __nv_bfloat16 hv, lv; split_bf16(v, hv, lv);
            waHb[co * (RWA * 2) + ci] = hv;
            waLb[co * (RWA * 2) + ci] = lv;
        }
        __syncthreads();

        #pragma unroll
        for (int kc = 0; kc < NK; kc++) {
            // A fragments (2 m-tiles, hi+lo)
            unsigned ah[2][4], al[2][4];
            #pragma unroll
            for (int mt = 0; mt < 2; mt++) {
                int arow = wm * 32 + mt * 16 + lg;
                const unsigned* pa = waH + arow * RWA + kc * 8 + lq;
                ah[mt][0] = pa[0];        ah[mt][2] = pa[4];
                ah[mt][1] = pa[8 * RWA];  ah[mt][3] = pa[8 * RWA + 4];
                const unsigned* pl = waL + arow * RWA + kc * 8 + lq;
                al[mt][0] = pl[0];        al[mt][2] = pl[4];
                al[mt][1] = pl[8 * RWA];  al[mt][3] = pl[8 * RWA + 4];
            }
            #pragma unroll
            for (int nt = 0; nt < 4; nt++) {
                int n = wn * 32 + nt * 8 + lg;
                const unsigned* pb = xtH + (n + t * DIL) * RWB + kc * 8 + lq;
                unsigned bh0 = pb[0], bh1 = pb[4];
                const unsigned* pbl = xtL + (n + t * DIL) * RWB + kc * 8 + lq;
                unsigned bl0 = pbl[0], bl1 = pbl[4];
                #pragma unroll
                for (int mt = 0; mt < 2; mt++) {
                    mma_bf16(acc[mt][nt], ah[mt], bh0, bh1);
                    mma_bf16(acc[mt][nt], ah[mt], bl0, bl1);
                    mma_bf16(acc[mt][nt], al[mt], bh0, bh1);
                }
            }
        }
    }

    // ---- conv1 epilogue: bias + relu + split -> hT (l-major) ----
    #pragma unroll
    for (int mt = 0; mt < 2; mt++) {
        int row = wm * 32 + mt * 16 + lg;
        float bb0 = b1s[row], bb1 = b1s[row + 8];
        #pragma unroll
        for (int nt = 0; nt < 4; nt++) {
            int col = wn * 32 + nt * 8 + 2 * lq;
            float* a = acc[mt][nt];
            float v00 = a[0] + bb0, v01 = a[1] + bb0;
            float v10 = a[2] + bb1, v11 = a[3] + bb1;
            v00 = v00 > 0.f ? v00 : 0.f;  v01 = v01 > 0.f ? v01 : 0.f;
            v10 = v10 > 0.f ? v10 : 0.f;  v11 = v11 > 0.f ? v11 : 0.f;
            __nv_bfloat16 hv, lv;
            split_bf16(v00, hv, lv);
            hHb[col * (RWH * 2) + row] = hv;       hLb[col * (RWH * 2) + row] = lv;
            split_bf16(v01, hv, lv);
            hHb[(col + 1) * (RWH * 2) + row] = hv; hLb[(col + 1) * (RWH * 2) + row] = lv;
            split_bf16(v10, hv, lv);
            hHb[col * (RWH * 2) + row + 8] = hv;   hLb[col * (RWH * 2) + row + 8] = lv;
            split_bf16(v11, hv, lv);
            hHb[(col + 1) * (RWH * 2) + row + 8] = hv;
            hLb[(col + 1) * (RWH * 2) + row + 8] = lv;
        }
    }
    __syncthreads();

    // ---- conv2: M=32, N=128, K=128 ----
    const int wm2 = warp & 1;      // m-tile (16 co2 each)
    const int wn2 = warp >> 1;     // 0..7 (n group of 16 l)
    float a2[2][4];
    #pragma unroll
    for (int nt = 0; nt < 2; nt++)
        #pragma unroll
        for (int q = 0; q < 4; q++) a2[nt][q] = 0.f;

    #pragma unroll
    for (int kc = 0; kc < 8; kc++) {
        unsigned ah[4], al[4];
        int arow = wm2 * 16 + lg;
        const unsigned* pa = w2H + arow * RW2 + kc * 8 + lq;
        ah[0] = pa[0];        ah[2] = pa[4];
        ah[1] = pa[8 * RW2];  ah[3] = pa[8 * RW2 + 4];
        const unsigned* pl = w2L + arow * RW2 + kc * 8 + lq;
        al[0] = pl[0];        al[2] = pl[4];
        al[1] = pl[8 * RW2];  al[3] = pl[8 * RW2 + 4];
        #pragma unroll
        for (int nt = 0; nt < 2; nt++) {
            int n = wn2 * 16 + nt * 8 + lg;
            const unsigned* pb = hH + n * RWH + kc * 8 + lq;
            unsigned bh0 = pb[0], bh1 = pb[4];
            const unsigned* pbl = hL + n * RWH + kc * 8 + lq;
            unsigned bl0 = pbl[0], bl1 = pbl[4];
            mma_bf16(a2[nt], ah, bh0, bh1);
            mma_bf16(a2[nt], ah, bl0, bl1);
            mma_bf16(a2[nt], al, bh0, bh1);
        }
    }

    // ---- conv2 epilogue: bias + relu -> global (float2 stores) ----
    float* yb = yout + (long)b * oss;
    {
        int row = wm2 * 16 + lg;
        float bb0 = b2s[row], bb1 = b2s[row + 8];
        #pragma unroll
        for (int nt = 0; nt < 2; nt++) {
            int col = wn2 * 16 + nt * 8 + 2 * lq;
            float v0 = a2[nt][0] + bb0, v1 = a2[nt][1] + bb0;
            float v2 = a2[nt][2] + bb1, v3 = a2[nt][3] + bb1;
            v0 = v0 > 0.f ? v0 : 0.f;  v1 = v1 > 0.f ? v1 : 0.f;
            v2 = v2 > 0.f ? v2 : 0.f;  v3 = v3 > 0.f ? v3 : 0.f;
            float2 p0 = make_float2(v0, v1);
            float2 p1 = make_float2(v2, v3);
            *(float2*)&yb[(long)row * LLEN + l0 + col]       = p0;
            *(float2*)&yb[(long)(row + 8) * LLEN + l0 + col] = p1;
        }
    }
}

// ------------------------------------------------------------------
// compress conv (192 -> 64, 1x1) fused with avgpool(2)+repeat(2)
// ------------------------------------------------------------------
#define CTILE 64
__global__ void __launch_bounds__(512, 2)
comp_kernel(const float* __restrict__ cat, const float* __restrict__ cw,
            const float* __restrict__ cb, float* __restrict__ out)
{
    extern __shared__ float sm[];
    float* xs  = sm;                   // 192 * 64
    float* ws  = xs + 192 * CTILE;     // 192 * 64   [k][co]
    float* cbs = ws + 192 * 64;        // 64

    const int b    = blockIdx.y;
    const int l0   = blockIdx.x * CTILE;
    const int tid  = threadIdx.x;
    const int warp = tid >> 5;
    const int ln   = tid & 31;
    const int wg   = warp >> 3;
    const int wc   = warp & 7;
    const int lb   = wg * 32 + ln;

    const float* catb = cat + (long)b * 192 * LLEN;
    for (int i = tid; i < 192 * CTILE; i += 512) {
        int ch = i / CTILE, j = i - ch * CTILE;
        xs[i] = catb[(long)ch * LLEN + l0 + j];
    }
    for (int i = tid; i < 64 * 192; i += 512) {
        int co = i & 63, k = i >> 6;
        ws[k * 64 + co] = cw[co * 192 + k];
    }
    if (tid < 64) cbs[tid] = cb[tid];
    __syncthreads();

    float acc[8];
    #pragma unroll
    for (int c = 0; c < 8; c++) acc[c] = 0.f;

    #pragma unroll 4
    for (int k = 0; k < 192; k++) {
        float4 wA = *(const float4*)(ws + k * 64 + wc * 8);
        float4 wB = *(const float4*)(ws + k * 64 + wc * 8 + 4);
        float xv = xs[k * CTILE + lb];
        acc[0] = fmaf(wA.x, xv, acc[0]);
        acc[1] = fmaf(wA.y, xv, acc[1]);
        acc[2] = fmaf(wA.z, xv, acc[2]);
        acc[3] = fmaf(wA.w, xv, acc[3]);
        acc[4] = fmaf(wB.x, xv, acc[4]);
        acc[5] = fmaf(wB.y, xv, acc[5]);
        acc[6] = fmaf(wB.z, xv, acc[6]);
        acc[7] = fmaf(wB.w, xv, acc[7]);
    }

    float* ob = out + (long)b * 64 * LLEN;
    #pragma unroll
    for (int c = 0; c < 8; c++) {
        int co = wc * 8 + c;
        float v = acc[c] + cbs[co];
        float p = __shfl_xor_sync(0xffffffffu, v, 1);
        ob[(long)co * LLEN + l0 + lb] = 0.5f * (v + p);
    }
}

// ------------------------------------------------------------------
// final per-sample 1x1 conv: 192 -> 1
// ------------------------------------------------------------------
__global__ void __launch_bounds__(256, 1)
final_kernel(const float* __restrict__ dec, const float* __restrict__ cw,
             const float* __restrict__ cbv, float* __restrict__ out)
{
    __shared__ float ws[192];
    const int b   = blockIdx.x;
    const int tid = threadIdx.x;
    const int c   = g_ids[b];
    if (tid < 192) ws[tid] = cw[(long)c * 192 + tid];
    __syncthreads();
    const float bb = cbv[c];
    const float* db = dec + (long)b * 192 * LLEN;
    for (int l = tid; l < LLEN; l += 256) {
        float s = bb;
        #pragma unroll 8
        for (int ch = 0; ch < 192; ch++) s = fmaf(ws[ch], db[(long)ch * LLEN + l], s);
        out[(long)b * LLEN + l] = s;
    }
}

// ------------------------------------------------------------------
static constexpr int smem_mma(int cin, int dil) {
    int cinp = cin < 16 ? 16 : cin;
    int xw   = 128 + 4 * dil;
    int rw   = cinp / 2 + 4;
    int words = 2 * xw * rw       // xt hi/lo
              + 2 * 128 * rw      // wa hi/lo
              + 2 * 128 * 68      // hT hi/lo
              + 2 * 32 * 68       // w2 hi/lo
              + 192;              // biases + pad
    return words * 4;
}
static constexpr int SMEM_C = (192 * CTILE + 192 * 64 + 64) * 4;

template<int CIN, int DIL>
static void launch_block(const float* xin, long iss, int ics,
                         const float* w1, const float* b1,
                         const float* w2, const float* b2,
                         float* yout, long oss,
                         const int* ids, long w1cs, long b1cs, long w2cs, long b2cs)
{
    static bool attr_done = false;
    if (!attr_done) {
        cudaFuncSetAttribute(block_mma_kernel<CIN, DIL>,
                             cudaFuncAttributeMaxDynamicSharedMemorySize,
                             smem_mma(CIN, DIL));
        attr_done = true;
    }
    dim3 grid(LLEN / 128, NB);
    block_mma_kernel<CIN, DIL><<<grid, 512, smem_mma(CIN, DIL)>>>(
        xin, iss, ics, w1, b1, w2, b2, yout, oss, ids, w1cs, b1cs, w2cs, b2cs);
}

extern "C" void kernel_launch(void* const* d_in, const int* in_sizes, int n_in,
                              void* d_out, int out_size)
{
    const float* x        = (const float*)d_in[0];
    const float* enc0_w1  = (const float*)d_in[1];
    const float* enc0_b1  = (const float*)d_in[2];
    const float* enc0_w2  = (const float*)d_in[3];
    const float* enc0_b2  = (const float*)d_in[4];
    const float* enc_w1   = (const float*)d_in[5];
    const float* enc_b1   = (const float*)d_in[6];
    const float* enc_w2   = (const float*)d_in[7];
    const float* enc_b2   = (const float*)d_in[8];
    const float* comp_w   = (const float*)d_in[9];
    const float* comp_b   = (const float*)d_in[10];
    const float* decf0_w1 = (const float*)d_in[11];
    const float* decf0_b1 = (const float*)d_in[12];
    const float* decf0_w2 = (const float*)d_in[13];
    const float* decf0_b2 = (const float*)d_in[14];
    const float* decf_w1  = (const float*)d_in[15];
    const float* decf_b1  = (const float*)d_in[16];
    const float* decf_w2  = (const float*)d_in[17];
    const float* decf_b2  = (const float*)d_in[18];
    const float* decv_w1  = (const float*)d_in[19];
    const float* decv_b1  = (const float*)d_in[20];
    const float* decv_w2  = (const float*)d_in[21];
    const float* decv_b2  = (const float*)d_in[22];
    const float* decv_cw  = (const float*)d_in[23];
    const float* decv_cb  = (const float*)d_in[24];
    float* out = (float*)d_out;

    float *cat, *dec, *encU;
    int* idsp;
    cudaGetSymbolAddress((void**)&cat,  g_cat);
    cudaGetSymbolAddress((void**)&dec,  g_dec);
    cudaGetSymbolAddress((void**)&encU, g_encU);
    cudaGetSymbolAddress((void**)&idsp, g_ids);

    cudaFuncSetAttribute(comp_kernel, cudaFuncAttributeMaxDynamicSharedMemorySize, SMEM_C);

    const long SS = (long)192 * LLEN;

    ids_kernel<<<1, 64>>>(x);

    // ---- encoder ----
    launch_block<1, 1>(x, (long)(LLEN + 1), 0,
                       enc0_w1, enc0_b1, enc0_w2, enc0_b2,
                       cat, SS, nullptr, 0, 0, 0, 0);
    launch_block<32, 2>(cat + 0 * 32 * LLEN, SS, LLEN,
                        enc_w1 + 0 * 20480, enc_b1 + 0 * 128, enc_w2 + 0 * 4096, enc_b2 + 0 * 32,
                        cat + 1 * 32 * LLEN, SS, nullptr, 0, 0, 0, 0);
    launch_block<32, 4>(cat + 1 * 32 * LLEN, SS, LLEN,
                        enc_w1 + 1 * 20480, enc_b1 + 1 * 128, enc_w2 + 1 * 4096, enc_b2 + 1 * 32,
                        cat + 2 * 32 * LLEN, SS, nullptr, 0, 0, 0, 0);
    launch_block<32, 8>(cat + 2 * 32 * LLEN, SS, LLEN,
                        enc_w1 + 2 * 20480, enc_b1 + 2 * 128, enc_w2 + 2 * 4096, enc_b2 + 2 * 32,
                        cat + 3 * 32 * LLEN, SS, nullptr, 0, 0, 0, 0);
    launch_block<32, 16>(cat + 3 * 32 * LLEN, SS, LLEN,
                         enc_w1 + 3 * 20480, enc_b1 + 3 * 128, enc_w2 + 3 * 4096, enc_b2 + 3 * 32,
                         cat + 4 * 32 * LLEN, SS, nullptr, 0, 0, 0, 0);
    launch_block<32, 32>(cat + 4 * 32 * LLEN, SS, LLEN,
                         enc_w1 + 4 * 20480, enc_b1 + 4 * 128, enc_w2 + 4 * 4096, enc_b2 + 4 * 32,
                         cat + 5 * 32 * LLEN, SS, nullptr, 0, 0, 0, 0);

    // ---- compress + pool + upsample ----
    {
        dim3 grid(LLEN / CTILE, NB);
        comp_kernel<<<grid, 512, SMEM_C>>>(cat, comp_w, comp_b, encU);
    }

    // ---- fixed decoder ----
    launch_block<64, 32>(encU, (long)64 * LLEN, LLEN,
                         decf0_w1, decf0_b1, decf0_w2, decf0_b2,
                         dec, SS, nullptr, 0, 0, 0, 0);
    launch_block<32, 16>(dec + 0 * 32 * LLEN, SS, LLEN,
                         decf_w1 + 0 * 20480, decf_b1 + 0 * 128, decf_w2 + 0 * 4096, decf_b2 + 0 * 32,
                         dec + 1 * 32 * LLEN, SS, nullptr, 0, 0, 0, 0);
    launch_block<32, 8>(dec + 1 * 32 * LLEN, SS, LLEN,
                        decf_w1 + 1 * 20480, decf_b1 + 1 * 128, decf_w2 + 1 * 4096, decf_b2 + 1 * 32,
                        dec + 2 * 32 * LLEN, SS, nullptr, 0, 0, 0, 0);
    launch_block<32, 4>(dec + 2 * 32 * LLEN, SS, LLEN,
                        decf_w1 + 2 * 20480, decf_b1 + 2 * 128, decf_w2 + 2 * 4096, decf_b2 + 2 * 32,
                        dec + 3 * 32 * LLEN, SS, nullptr, 0, 0, 0, 0);

    // ---- variable decoder: per-sample selected combination ----
    launch_block<32, 2>(dec + 3 * 32 * LLEN, SS, LLEN,
                        decv_w1 + 0 * 20480, decv_b1 + 0 * 128, decv_w2 + 0 * 4096, decv_b2 + 0 * 32,
                        dec + 4 * 32 * LLEN, SS,
                        idsp, 40960, 256, 8192, 64);
    launch_block<32, 1>(dec + 4 * 32 * LLEN, SS, LLEN,
                        decv_w1 + 1 * 20480, decv_b1 + 1 * 128, decv_w2 + 1 * 4096, decv_b2 + 1 * 32,
                        dec + 5 * 32 * LLEN, SS,
                        idsp, 40960, 256, 8192, 64);

    // ---- final 1x1 conv (per-sample weights) ----
    final_kernel<<<NB, 256>>>(dec, decv_cw, decv_cb, out);
}

// round 6
// speedup vs baseline: 2.3424x; 1.0860x over previous
#include <cuda_runtime.h>
#include <cuda_bf16.h>

#define LLEN 1024
#define NB   64

// ---- device scratch (no allocations allowed) ----
__device__ float g_cat [NB * 192 * LLEN];
__device__ float g_dec [NB * 192 * LLEN];
__device__ float g_encU[NB * 64  * LLEN];
__device__ int   g_ids [NB];

// ------------------------------------------------------------------
__global__ void ids_kernel(const float* __restrict__ x) {
    int b = threadIdx.x;
    if (b < NB) g_ids[b] = (int)x[(long)b * (LLEN + 1) + LLEN];
}

// ------------------------------------------------------------------
__device__ __forceinline__ void mma_bf16(float* c, const unsigned* a,
                                         unsigned b0, unsigned b1) {
    asm volatile(
        "mma.sync.aligned.m16n8k16.row.col.f32.bf16.bf16.f32 "
        "{%0,%1,%2,%3}, {%4,%5,%6,%7}, {%8,%9}, {%0,%1,%2,%3};\n"
        : "+f"(c[0]), "+f"(c[1]), "+f"(c[2]), "+f"(c[3])
        : "r"(a[0]), "r"(a[1]), "r"(a[2]), "r"(a[3]), "r"(b0), "r"(b1));
}
__device__ __forceinline__ void ldsm4(unsigned* r, unsigned addr) {
    asm volatile("ldmatrix.sync.aligned.m8n8.x4.shared.b16 {%0,%1,%2,%3}, [%4];\n"
                 : "=r"(r[0]), "=r"(r[1]), "=r"(r[2]), "=r"(r[3]) : "r"(addr));
}
__device__ __forceinline__ void ldsm2(unsigned* r, unsigned addr) {
    asm volatile("ldmatrix.sync.aligned.m8n8.x2.shared.b16 {%0,%1}, [%2];\n"
                 : "=r"(r[0]), "=r"(r[1]) : "r"(addr));
}
__device__ __forceinline__ unsigned su32(const void* p) {
    return (unsigned)__cvta_generic_to_shared(p);
}
__device__ __forceinline__ void split_bf16(float v, __nv_bfloat16& hi, __nv_bfloat16& lo) {
    hi = __float2bfloat16(v);
    lo = __float2bfloat16(v - __bfloat162float(hi));
}

// ------------------------------------------------------------------
// Fused TCN block via tensor cores (bf16 hi/lo split, fp32 accum, LDSM):
//   conv1: CIN -> 128 (k=5, dil DIL) + bias + relu, in two co-halves of 64
//   conv2: 128 -> 32 (1x1) + bias + relu (accumulated across halves)
// CTA = TIL l-positions, 512 thr = 16 warps. 2 CTAs/SM.
// conv1 warps: wm(2) x wn(8); warp tile m32 x n(TIL/8).
// conv2 warps: wm2(2) x wn2(8); warp tile m16 x n(TIL/8).
// ------------------------------------------------------------------
template<int CIN, int DIL, int TIL>
__global__ void __launch_bounds__(512, 2)
block_mma_kernel(const float* __restrict__ xin, long iss, int ics,
                 const float* __restrict__ w1, const float* __restrict__ b1,
                 const float* __restrict__ w2, const float* __restrict__ b2,
                 float* __restrict__ yout, long oss,
                 const int* __restrict__ ids,
                 long w1_cs, long b1_cs, long w2_cs, long b2_cs)
{
    constexpr int CINP = (CIN < 16) ? 16 : CIN;
    constexpr int NK   = CINP / 16;
    constexpr int XW   = TIL + 4 * DIL;
    constexpr int SB   = CINP + 8;     // xt / wa row stride (bf16)
    constexpr int SH   = 72;           // hT row stride
    constexpr int S2   = 136;          // w2 row stride
    constexpr int NT   = TIL / 64;     // n-tiles (m8) per warp per 8-n group

    extern __shared__ __nv_bfloat16 smb[];
    __nv_bfloat16* xtH = smb;
    __nv_bfloat16* xtL = xtH + XW * SB;
    __nv_bfloat16* waH = xtL + XW * SB;
    __nv_bfloat16* waL = waH + 64 * SB;
    __nv_bfloat16* hH  = waL + 64 * SB;
    __nv_bfloat16* hL  = hH  + TIL * SH;
    __nv_bfloat16* w2H = hL  + TIL * SH;
    __nv_bfloat16* w2L = w2H + 32 * S2;
    float* b1s = (float*)(w2L + 32 * S2);    // 128
    float* b2s = b1s + 128;                  // 32

    const int b    = blockIdx.y;
    const int l0   = blockIdx.x * TIL;
    const int tid  = threadIdx.x;
    const int warp = tid >> 5;
    const int ln   = tid & 31;
    const int lq   = ln & 3;
    const int lg   = ln >> 2;
    const int lr   = ln & 7;        // ldmatrix row-within-8
    const int lt   = ln >> 3;       // ldmatrix tile index

    const float* w1p = w1;
    const float* b1p = b1;
    const float* w2p = w2;
    const float* b2p = b2;
    if (ids) {
        int c = ids[b];
        w1p += (long)c * w1_cs;  b1p += (long)c * b1_cs;
        w2p += (long)c * w2_cs;  b2p += (long)c * b2_cs;
    }

    // ---- stage x (transposed, split) ----
    const float* xb = xin + (long)b * iss;
    for (int ci = warp; ci < CINP; ci += 16) {
        for (int r = ln; r < XW; r += 32) {
            int pos = l0 - 2 * DIL + r;
            float v = (ci < CIN && pos >= 0 && pos < LLEN)
                      ? xb[(long)ci * ics + pos] : 0.f;
            __nv_bfloat16 hv, lv; split_bf16(v, hv, lv);
            xtH[r * SB + ci] = hv;
            xtL[r * SB + ci] = lv;
        }
    }
    // ---- stage W2 (split) + biases ----
    for (int i = tid; i < 32 * 128; i += 512) {
        int co = i >> 7, k = i & 127;
        __nv_bfloat16 hv, lv; split_bf16(w2p[i], hv, lv);
        w2H[co * S2 + k] = hv;
        w2L[co * S2 + k] = lv;
    }
    if (tid < 128) b1s[tid] = b1p[tid];
    if (tid < 32)  b2s[tid] = b2p[tid];

    const int wm  = warp >> 3;      // conv1 m-group (32 co)
    const int wn  = warp & 7;       // conv1 n-group (TIL/8 l)
    const int wm2 = warp & 1;       // conv2 m-group (16 co2)
    const int wn2 = warp >> 1;      // conv2 n-group (TIL/8 l)

    float a2[NT][4];
    #pragma unroll
    for (int nt = 0; nt < NT; nt++)
        #pragma unroll
        for (int q = 0; q < 4; q++) a2[nt][q] = 0.f;

    #pragma unroll
    for (int half = 0; half < 2; half++) {
        const int coB = half * 64;

        float acc[2][NT][4];
        #pragma unroll
        for (int mt = 0; mt < 2; mt++)
            #pragma unroll
            for (int nt = 0; nt < NT; nt++)
                #pragma unroll
                for (int q = 0; q < 4; q++) acc[mt][nt][q] = 0.f;

        #pragma unroll
        for (int t = 0; t < 5; t++) {
            __syncthreads();   // wa reusable (prev t mma / prev half conv2 done)
            for (int i = tid; i < 64 * CINP; i += 512) {
                int co = i / CINP, ci = i - co * CINP;
                float v = (ci < CIN)
                          ? w1p[(long)(coB + co) * (CIN * 5) + ci * 5 + t] : 0.f;
                __nv_bfloat16 hv, lv; split_bf16(v, hv, lv);
                waH[co * SB + ci] = hv;
                waL[co * SB + ci] = lv;
            }
            __syncthreads();

            #pragma unroll
            for (int kc = 0; kc < NK; kc++) {
                unsigned ah[2][4], al[2][4];
                #pragma unroll
                for (int mt = 0; mt < 2; mt++) {
                    int arow = wm * 32 + mt * 16 + lr + (lt & 1) * 8;
                    int acol = kc * 16 + (lt >> 1) * 8;
                    ldsm4(ah[mt], su32(waH + arow * SB + acol));
                    ldsm4(al[mt], su32(waL + arow * SB + acol));
                }
                unsigned bh[4], bl[4];
                if (NT == 2) {
                    int brow = wn * 16 + lr + (lt & 1) * 8 + t * DIL;
                    int bcol = kc * 16 + (lt >> 1) * 8;
                    ldsm4(bh, su32(xtH + brow * SB + bcol));
                    ldsm4(bl, su32(xtL + brow * SB + bcol));
                } else {
                    int brow = wn * 8 + lr + t * DIL;
                    int bcol = kc * 16 + ((ln >> 3) & 1) * 8;
                    ldsm2(bh, su32(xtH + brow * SB + bcol));
                    ldsm2(bl, su32(xtL + brow * SB + bcol));
                }
                #pragma unroll
                for (int nt = 0; nt < NT; nt++) {
                    unsigned bh0 = (NT == 2) ? bh[nt] : bh[0];
                    unsigned bh1 = (NT == 2) ? bh[nt + 2] : bh[1];
                    unsigned bl0 = (NT == 2) ? bl[nt] : bl[0];
                    unsigned bl1 = (NT == 2) ? bl[nt + 2] : bl[1];
                    #pragma unroll
                    for (int mt = 0; mt < 2; mt++) {
                        mma_bf16(acc[mt][nt], ah[mt], bh0, bh1);
                        mma_bf16(acc[mt][nt], ah[mt], bl0, bl1);
                        mma_bf16(acc[mt][nt], al[mt], bh0, bh1);
                    }
                }
            }
        }

        // ---- conv1 epilogue: bias + relu + split -> hT (l-major) ----
        #pragma unroll
        for (int mt = 0; mt < 2; mt++) {
            int m = wm * 32 + mt * 16 + lg;      // local co (0..63)
            float bb0 = b1s[coB + m], bb1 = b1s[coB + m + 8];
            #pragma unroll
            for (int nt = 0; nt < NT; nt++) {
                int n = ((NT == 2) ? wn * 16 + nt * 8 : wn * 8) + 2 * lq;
                float* a = acc[mt][nt];
                float v00 = a[0] + bb0, v01 = a[1] + bb0;
                float v10 = a[2] + bb1, v11 = a[3] + bb1;
                v00 = v00 > 0.f ? v00 : 0.f;  v01 = v01 > 0.f ? v01 : 0.f;
                v10 = v10 > 0.f ? v10 : 0.f;  v11 = v11 > 0.f ? v11 : 0.f;
                __nv_bfloat16 hv, lv;
                split_bf16(v00, hv, lv); hH[n * SH + m] = hv;           hL[n * SH + m] = lv;
                split_bf16(v01, hv, lv); hH[(n + 1) * SH + m] = hv;     hL[(n + 1) * SH + m] = lv;
                split_bf16(v10, hv, lv); hH[n * SH + m + 8] = hv;       hL[n * SH + m + 8] = lv;
                split_bf16(v11, hv, lv); hH[(n + 1) * SH + m + 8] = hv; hL[(n + 1) * SH + m + 8] = lv;
            }
        }
        __syncthreads();

        // ---- conv2 partial (k over this half's 64 channels) ----
        #pragma unroll
        for (int kc = 0; kc < 4; kc++) {
            unsigned ah[4], al[4];
            {
                int arow = wm2 * 16 + lr + (lt & 1) * 8;
                int acol = coB + kc * 16 + (lt >> 1) * 8;
                ldsm4(ah, su32(w2H + arow * S2 + acol));
                ldsm4(al, su32(w2L + arow * S2 + acol));
            }
            unsigned bh[4], bl[4];
            if (NT == 2) {
                int brow = wn2 * 16 + lr + (lt & 1) * 8;
                int bcol = kc * 16 + (lt >> 1) * 8;
                ldsm4(bh, su32(hH + brow * SH + bcol));
                ldsm4(bl, su32(hL + brow * SH + bcol));
            } else {
                int brow = wn2 * 8 + lr;
                int bcol = kc * 16 + ((ln >> 3) & 1) * 8;
                ldsm2(bh, su32(hH + brow * SH + bcol));
                ldsm2(bl, su32(hL + brow * SH + bcol));
            }
            #pragma unroll
            for (int nt = 0; nt < NT; nt++) {
                unsigned bh0 = (NT == 2) ? bh[nt] : bh[0];
                unsigned bh1 = (NT == 2) ? bh[nt + 2] : bh[1];
                unsigned bl0 = (NT == 2) ? bl[nt] : bl[0];
                unsigned bl1 = (NT == 2) ? bl[nt + 2] : bl[1];
                mma_bf16(a2[nt], ah, bh0, bh1);
                mma_bf16(a2[nt], ah, bl0, bl1);
                mma_bf16(a2[nt], al, bh0, bh1);
            }
        }
        // next half's first t-loop barrier protects hT reuse
    }

    // ---- conv2 epilogue: bias + relu -> global ----
    float* yb = yout + (long)b * oss;
    {
        int row = wm2 * 16 + lg;
        float bb0 = b2s[row], bb1 = b2s[row + 8];
        #pragma unroll
        for (int nt = 0; nt < NT; nt++) {
            int col = ((NT == 2) ? wn2 * 16 + nt * 8 : wn2 * 8) + 2 * lq;
            float v0 = a2[nt][0] + bb0, v1 = a2[nt][1] + bb0;
            float v2 = a2[nt][2] + bb1, v3 = a2[nt][3] + bb1;
            v0 = v0 > 0.f ? v0 : 0.f;  v1 = v1 > 0.f ? v1 : 0.f;
            v2 = v2 > 0.f ? v2 : 0.f;  v3 = v3 > 0.f ? v3 : 0.f;
            *(float2*)&yb[(long)row * LLEN + l0 + col]       = make_float2(v0, v1);
            *(float2*)&yb[(long)(row + 8) * LLEN + l0 + col] = make_float2(v2, v3);
        }
    }
}

// ------------------------------------------------------------------
// compress conv (192 -> 64, 1x1) fused with avgpool(2)+repeat(2)
// ------------------------------------------------------------------
#define CTILE 64
__global__ void __launch_bounds__(512, 2)
comp_kernel(const float* __restrict__ cat, const float* __restrict__ cw,
            const float* __restrict__ cb, float* __restrict__ out)
{
    extern __shared__ float sm[];
    float* xs  = sm;                   // 192 * 64
    float* ws  = xs + 192 * CTILE;     // 192 * 64   [k][co]
    float* cbs = ws + 192 * 64;        // 64

    const int b    = blockIdx.y;
    const int l0   = blockIdx.x * CTILE;
    const int tid  = threadIdx.x;
    const int warp = tid >> 5;
    const int ln   = tid & 31;
    const int wg   = warp >> 3;
    const int wc   = warp & 7;
    const int lb   = wg * 32 + ln;

    const float* catb = cat + (long)b * 192 * LLEN;
    for (int i = tid; i < 192 * CTILE; i += 512) {
        int ch = i / CTILE, j = i - ch * CTILE;
        xs[i] = catb[(long)ch * LLEN + l0 + j];
    }
    for (int i = tid; i < 64 * 192; i += 512) {
        int co = i & 63, k = i >> 6;
        ws[k * 64 + co] = cw[co * 192 + k];
    }
    if (tid < 64) cbs[tid] = cb[tid];
    __syncthreads();

    float acc[8];
    #pragma unroll
    for (int c = 0; c < 8; c++) acc[c] = 0.f;

    #pragma unroll 4
    for (int k = 0; k < 192; k++) {
        float4 wA = *(const float4*)(ws + k * 64 + wc * 8);
        float4 wB = *(const float4*)(ws + k * 64 + wc * 8 + 4);
        float xv = xs[k * CTILE + lb];
        acc[0] = fmaf(wA.x, xv, acc[0]);
        acc[1] = fmaf(wA.y, xv, acc[1]);
        acc[2] = fmaf(wA.z, xv, acc[2]);
        acc[3] = fmaf(wA.w, xv, acc[3]);
        acc[4] = fmaf(wB.x, xv, acc[4]);
        acc[5] = fmaf(wB.y, xv, acc[5]);
        acc[6] = fmaf(wB.z, xv, acc[6]);
        acc[7] = fmaf(wB.w, xv, acc[7]);
    }

    float* ob = out + (long)b * 64 * LLEN;
    #pragma unroll
    for (int c = 0; c < 8; c++) {
        int co = wc * 8 + c;
        float v = acc[c] + cbs[co];
        float p = __shfl_xor_sync(0xffffffffu, v, 1);
        ob[(long)co * LLEN + l0 + lb] = 0.5f * (v + p);
    }
}

// ------------------------------------------------------------------
// final per-sample 1x1 conv: 192 -> 1. Grid (4, NB), 256 thr.
// ------------------------------------------------------------------
__global__ void __launch_bounds__(256, 1)
final_kernel(const float* __restrict__ dec, const float* __restrict__ cw,
             const float* __restrict__ cbv, float* __restrict__ out)
{
    __shared__ float ws[192];
    const int b   = blockIdx.y;
    const int tid = threadIdx.x;
    const int l   = blockIdx.x * 256 + tid;
    const int c   = g_ids[b];
    if (tid < 192) ws[tid] = cw[(long)c * 192 + tid];
    __syncthreads();
    float s = cbv[c];
    const float* db = dec + (long)b * 192 * LLEN + l;
    #pragma unroll 8
    for (int ch = 0; ch < 192; ch++) s = fmaf(ws[ch], db[(long)ch * LLEN], s);
    out[(long)b * LLEN + l] = s;
}

// ------------------------------------------------------------------
static constexpr int smem_mma(int cin, int dil, int til) {
    int cinp = cin < 16 ? 16 : cin;
    int sb   = cinp + 8;
    int xw   = til + 4 * dil;
    int elems = 2 * xw * sb + 2 * 64 * sb + 2 * til * 72 + 2 * 32 * 136;
    return elems * 2 + 160 * 4;
}
static constexpr int SMEM_C = (192 * CTILE + 192 * 64 + 64) * 4;

template<int CIN, int DIL, int TIL>
static void launch_block(const float* xin, long iss, int ics,
                         const float* w1, const float* b1,
                         const float* w2, const float* b2,
                         float* yout, long oss,
                         const int* ids, long w1cs, long b1cs, long w2cs, long b2cs)
{
    static bool attr_done = false;
    if (!attr_done) {
        cudaFuncSetAttribute(block_mma_kernel<CIN, DIL, TIL>,
                             cudaFuncAttributeMaxDynamicSharedMemorySize,
                             smem_mma(CIN, DIL, TIL));
        attr_done = true;
    }
    dim3 grid(LLEN / TIL, NB);
    block_mma_kernel<CIN, DIL, TIL><<<grid, 512, smem_mma(CIN, DIL, TIL)>>>(
        xin, iss, ics, w1, b1, w2, b2, yout, oss, ids, w1cs, b1cs, w2cs, b2cs);
}

extern "C" void kernel_launch(void* const* d_in, const int* in_sizes, int n_in,
                              void* d_out, int out_size)
{
    const float* x        = (const float*)d_in[0];
    const float* enc0_w1  = (const float*)d_in[1];
    const float* enc0_b1  = (const float*)d_in[2];
    const float* enc0_w2  = (const float*)d_in[3];
    const float* enc0_b2  = (const float*)d_in[4];
    const float* enc_w1   = (const float*)d_in[5];
    const float* enc_b1   = (const float*)d_in[6];
    const float* enc_w2   = (const float*)d_in[7];
    const float* enc_b2   = (const float*)d_in[8];
    const float* comp_w   = (const float*)d_in[9];
    const float* comp_b   = (const float*)d_in[10];
    const float* decf0_w1 = (const float*)d_in[11];
    const float* decf0_b1 = (const float*)d_in[12];
    const float* decf0_w2 = (const float*)d_in[13];
    const float* decf0_b2 = (const float*)d_in[14];
    const float* decf_w1  = (const float*)d_in[15];
    const float* decf_b1  = (const float*)d_in[16];
    const float* decf_w2  = (const float*)d_in[17];
    const float* decf_b2  = (const float*)d_in[18];
    const float* decv_w1  = (const float*)d_in[19];
    const float* decv_b1  = (const float*)d_in[20];
    const float* decv_w2  = (const float*)d_in[21];
    const float* decv_b2  = (const float*)d_in[22];
    const float* decv_cw  = (const float*)d_in[23];
    const float* decv_cb  = (const float*)d_in[24];
    float* out = (float*)d_out;

    float *cat, *dec, *encU;
    int* idsp;
    cudaGetSymbolAddress((void**)&cat,  g_cat);
    cudaGetSymbolAddress((void**)&dec,  g_dec);
    cudaGetSymbolAddress((void**)&encU, g_encU);
    cudaGetSymbolAddress((void**)&idsp, g_ids);

    cudaFuncSetAttribute(comp_kernel, cudaFuncAttributeMaxDynamicSharedMemorySize, SMEM_C);

    const long SS = (long)192 * LLEN;

    ids_kernel<<<1, 64>>>(x);

    // ---- encoder ----
    launch_block<1, 1, 128>(x, (long)(LLEN + 1), 0,
                            enc0_w1, enc0_b1, enc0_w2, enc0_b2,
                            cat, SS, nullptr, 0, 0, 0, 0);
    launch_block<32, 2, 128>(cat + 0 * 32 * LLEN, SS, LLEN,
                             enc_w1 + 0 * 20480, enc_b1 + 0 * 128, enc_w2 + 0 * 4096, enc_b2 + 0 * 32,
                             cat + 1 * 32 * LLEN, SS, nullptr, 0, 0, 0, 0);
    launch_block<32, 4, 128>(cat + 1 * 32 * LLEN, SS, LLEN,
                             enc_w1 + 1 * 20480, enc_b1 + 1 * 128, enc_w2 + 1 * 4096, enc_b2 + 1 * 32,
                             cat + 2 * 32 * LLEN, SS, nullptr, 0, 0, 0, 0);
    launch_block<32, 8, 128>(cat + 2 * 32 * LLEN, SS, LLEN,
                             enc_w1 + 2 * 20480, enc_b1 + 2 * 128, enc_w2 + 2 * 4096, enc_b2 + 2 * 32,
                             cat + 3 * 32 * LLEN, SS, nullptr, 0, 0, 0, 0);
    launch_block<32, 16, 128>(cat + 3 * 32 * LLEN, SS, LLEN,
                              enc_w1 + 3 * 20480, enc_b1 + 3 * 128, enc_w2 + 3 * 4096, enc_b2 + 3 * 32,
                              cat + 4 * 32 * LLEN, SS, nullptr, 0, 0, 0, 0);
    launch_block<32, 32, 128>(cat + 4 * 32 * LLEN, SS, LLEN,
                              enc_w1 + 4 * 20480, enc_b1 + 4 * 128, enc_w2 + 4 * 4096, enc_b2 + 4 * 32,
                              cat + 5 * 32 * LLEN, SS, nullptr, 0, 0, 0, 0);

    // ---- compress + pool + upsample ----
    {
        dim3 grid(LLEN / CTILE, NB);
        comp_kernel<<<grid, 512, SMEM_C>>>(cat, comp_w, comp_b, encU);
    }

    // ---- fixed decoder ----
    launch_block<64, 32, 64>(encU, (long)64 * LLEN, LLEN,
                             decf0_w1, decf0_b1, decf0_w2, decf0_b2,
                             dec, SS, nullptr, 0, 0, 0, 0);
    launch_block<32, 16, 128>(dec + 0 * 32 * LLEN, SS, LLEN,
                              decf_w1 + 0 * 20480, decf_b1 + 0 * 128, decf_w2 + 0 * 4096, decf_b2 + 0 * 32,
                              dec + 1 * 32 * LLEN, SS, nullptr, 0, 0, 0, 0);
    launch_block<32, 8, 128>(dec + 1 * 32 * LLEN, SS, LLEN,
                             decf_w1 + 1 * 20480, decf_b1 + 1 * 128, decf_w2 + 1 * 4096, decf_b2 + 1 * 32,
                             dec + 2 * 32 * LLEN, SS, nullptr, 0, 0, 0, 0);
    launch_block<32, 4, 128>(dec + 2 * 32 * LLEN, SS, LLEN,
                             decf_w1 + 2 * 20480, decf_b1 + 2 * 128, decf_w2 + 2 * 4096, decf_b2 + 2 * 32,
                             dec + 3 * 32 * LLEN, SS, nullptr, 0, 0, 0, 0);

    // ---- variable decoder: per-sample selected combination ----
    launch_block<32, 2, 128>(dec + 3 * 32 * LLEN, SS, LLEN,
                             decv_w1 + 0 * 20480, decv_b1 + 0 * 128, decv_w2 + 0 * 4096, decv_b2 + 0 * 32,
                             dec + 4 * 32 * LLEN, SS,
                             idsp, 40960, 256, 8192, 64);
    launch_block<32, 1, 128>(dec + 4 * 32 * LLEN, SS, LLEN,
                             decv_w1 + 1 * 20480, decv_b1 + 1 * 128, decv_w2 + 1 * 4096, decv_b2 + 1 * 32,
                             dec + 5 * 32 * LLEN, SS,
                             idsp, 40960, 256, 8192, 64);

    // ---- final 1x1 conv (per-sample weights) ----
    {
        dim3 grid(4, NB);
        final_kernel<<<grid, 256>>>(dec, decv_cw, decv_cb, out);
    }
}

// round 7
// speedup vs baseline: 2.5997x; 1.1099x over previous
#include <cuda_runtime.h>
#include <cuda_bf16.h>

#define LLEN 1024
#define NB   64

// ---- device scratch (no allocations allowed) ----
__device__ float g_cat [NB * 192 * LLEN];
__device__ float g_dec [NB * 192 * LLEN];
__device__ float g_encU[NB * 64  * LLEN];
__device__ int   g_ids [NB];

// ------------------------------------------------------------------
__global__ void ids_kernel(const float* __restrict__ x) {
    int b = threadIdx.x;
    if (b < NB) g_ids[b] = (int)x[(long)b * (LLEN + 1) + LLEN];
}

// ------------------------------------------------------------------
__device__ __forceinline__ void mma_bf16(float* c, const unsigned* a,
                                         unsigned b0, unsigned b1) {
    asm volatile(
        "mma.sync.aligned.m16n8k16.row.col.f32.bf16.bf16.f32 "
        "{%0,%1,%2,%3}, {%4,%5,%6,%7}, {%8,%9}, {%0,%1,%2,%3};\n"
        : "+f"(c[0]), "+f"(c[1]), "+f"(c[2]), "+f"(c[3])
        : "r"(a[0]), "r"(a[1]), "r"(a[2]), "r"(a[3]), "r"(b0), "r"(b1));
}
__device__ __forceinline__ void ldsm4(unsigned* r, unsigned addr) {
    asm volatile("ldmatrix.sync.aligned.m8n8.x4.shared.b16 {%0,%1,%2,%3}, [%4];\n"
                 : "=r"(r[0]), "=r"(r[1]), "=r"(r[2]), "=r"(r[3]) : "r"(addr));
}
__device__ __forceinline__ void ldsm2(unsigned* r, unsigned addr) {
    asm volatile("ldmatrix.sync.aligned.m8n8.x2.shared.b16 {%0,%1}, [%2];\n"
                 : "=r"(r[0]), "=r"(r[1]) : "r"(addr));
}
__device__ __forceinline__ unsigned su32(const void* p) {
    return (unsigned)__cvta_generic_to_shared(p);
}
__device__ __forceinline__ void split_bf16(float v, __nv_bfloat16& hi, __nv_bfloat16& lo) {
    hi = __float2bfloat16(v);
    lo = __float2bfloat16(v - __bfloat162float(hi));
}
__device__ __forceinline__ constexpr int ilog2c(int v) {
    return (v == 16) ? 4 : (v == 32) ? 5 : 6;
}

// ------------------------------------------------------------------
// Fused TCN block via tensor cores (bf16 hi/lo split, fp32 accum, LDSM,
// software-pipelined weight staging):
//   conv1: CIN -> 128 (k=5, dil DIL) + bias + relu, two co-halves of 64
//   conv2: 128 -> 32 (1x1) + bias + relu (accumulated across halves)
// CTA = TIL l, 512 thr = 16 warps, 2 CTAs/SM.
// ------------------------------------------------------------------
template<int CIN, int DIL, int TIL>
__global__ void __launch_bounds__(512, 2)
block_mma_kernel(const float* __restrict__ xin, long iss, int ics,
                 const float* __restrict__ w1, const float* __restrict__ b1,
                 const float* __restrict__ w2, const float* __restrict__ b2,
                 float* __restrict__ yout, long oss,
                 const int* __restrict__ ids,
                 long w1_cs, long b1_cs, long w2_cs, long b2_cs)
{
    constexpr int CINP = (CIN < 16) ? 16 : CIN;
    constexpr int LC   = ilog2c(CINP);
    constexpr int NK   = CINP / 16;
    constexpr int XW   = TIL + 4 * DIL;
    constexpr int SB   = CINP + 8;       // xt / wa row stride (bf16)
    constexpr int SH   = 72;             // hT row stride
    constexpr int S2   = 136;            // w2 row stride
    constexpr int NT   = TIL / 64;       // n-tiles per warp
    constexpr bool DBUF = (CIN <= 32);   // double-buffer weights?
    constexpr int NBUF = DBUF ? 2 : 1;
    constexpr int WBUF = 64 * SB;        // wa elems per plane per buffer
    constexpr int PW   = (64 * CINP) / 512;  // prefetch floats per thread

    extern __shared__ __nv_bfloat16 smb[];
    __nv_bfloat16* xtH = smb;
    __nv_bfloat16* xtL = xtH + XW * SB;
    __nv_bfloat16* waB = xtL + XW * SB;               // H planes then L planes
    __nv_bfloat16* hH  = waB + 2 * NBUF * WBUF;
    __nv_bfloat16* hL  = hH  + TIL * SH;
    __nv_bfloat16* w2H = hL  + TIL * SH;
    __nv_bfloat16* w2L = w2H + 32 * S2;
    float* b1s = (float*)(w2L + 32 * S2);    // 128
    float* b2s = b1s + 128;                  // 32

    const int b    = blockIdx.y;
    const int l0   = blockIdx.x * TIL;
    const int tid  = threadIdx.x;
    const int warp = tid >> 5;
    const int ln   = tid & 31;
    const int lq   = ln & 3;
    const int lg   = ln >> 2;
    const int lr   = ln & 7;
    const int lt   = ln >> 3;

    const float* w1p = w1;
    const float* b1p = b1;
    const float* w2p = w2;
    const float* b2p = b2;
    if (ids) {
        int c = ids[b];
        w1p += (long)c * w1_cs;  b1p += (long)c * b1_cs;
        w2p += (long)c * w2_cs;  b2p += (long)c * b2_cs;
    }

    // prefetch lane decode (same for every t)
    int pco[PW], pci[PW];
    #pragma unroll
    for (int j = 0; j < PW; j++) {
        int i = tid + j * 512;
        pco[j] = i >> LC;
        pci[j] = i & (CINP - 1);
    }

    // ---- stage x (transposed, split) ----
    const float* xb = xin + (long)b * iss;
    for (int ci = warp; ci < CINP; ci += 16) {
        for (int r = ln; r < XW; r += 32) {
            int pos = l0 - 2 * DIL + r;
            float v = (ci < CIN && pos >= 0 && pos < LLEN)
                      ? xb[(long)ci * ics + pos] : 0.f;
            __nv_bfloat16 hv, lv; split_bf16(v, hv, lv);
            xtH[r * SB + ci] = hv;
            xtL[r * SB + ci] = lv;
        }
    }
    // ---- stage W2 (split) + biases ----
    for (int i = tid; i < 32 * 128; i += 512) {
        int co = i >> 7, k = i & 127;
        __nv_bfloat16 hv, lv; split_bf16(w2p[i], hv, lv);
        w2H[co * S2 + k] = hv;
        w2L[co * S2 + k] = lv;
    }
    if (tid < 128) b1s[tid] = b1p[tid];
    if (tid < 32)  b2s[tid] = b2p[tid];

    const int wm  = warp >> 3;
    const int wn  = warp & 7;
    const int wm2 = warp & 1;
    const int wn2 = warp >> 1;

    float a2[NT][4];
    #pragma unroll
    for (int nt = 0; nt < NT; nt++)
        #pragma unroll
        for (int q = 0; q < 4; q++) a2[nt][q] = 0.f;

    #pragma unroll
    for (int half = 0; half < 2; half++) {
        const int coB = half * 64;

        float acc[2][NT][4];
        #pragma unroll
        for (int mt = 0; mt < 2; mt++)
            #pragma unroll
            for (int nt = 0; nt < NT; nt++)
                #pragma unroll
                for (int q = 0; q < 4; q++) acc[mt][nt][q] = 0.f;

        // ---- preload t=0 weights ----
        {
            float pre[PW];
            #pragma unroll
            for (int j = 0; j < PW; j++)
                pre[j] = (pci[j] < CIN)
                    ? w1p[(long)(coB + pco[j]) * (CIN * 5) + pci[j] * 5 + 0] : 0.f;
            __syncthreads();   // wa[buf0] reusable (prev half / prev conv2 done)
            #pragma unroll
            for (int j = 0; j < PW; j++) {
                __nv_bfloat16 hv, lv; split_bf16(pre[j], hv, lv);
                waB[pco[j] * SB + pci[j]] = hv;
                waB[NBUF * WBUF + pco[j] * SB + pci[j]] = lv;
            }
            __syncthreads();
        }

        #pragma unroll
        for (int t = 0; t < 5; t++) {
            // prefetch next tap's weights into registers (overlaps mma)
            float nxt[PW];
            if (t < 4) {
                #pragma unroll
                for (int j = 0; j < PW; j++)
                    nxt[j] = (pci[j] < CIN)
                        ? w1p[(long)(coB + pco[j]) * (CIN * 5) + pci[j] * 5 + (t + 1)]
                        : 0.f;
            }

            const __nv_bfloat16* wH = waB + (DBUF ? (t & 1) * WBUF : 0);
            const __nv_bfloat16* wL = wH + NBUF * WBUF;

            #pragma unroll
            for (int kc = 0; kc < NK; kc++) {
                unsigned ah[2][4], al[2][4];
                #pragma unroll
                for (int mt = 0; mt < 2; mt++) {
                    int arow = wm * 32 + mt * 16 + lr + (lt & 1) * 8;
                    int acol = kc * 16 + (lt >> 1) * 8;
                    ldsm4(ah[mt], su32(wH + arow * SB + acol));
                    ldsm4(al[mt], su32(wL + arow * SB + acol));
                }
                unsigned bh[4], bl[4];
                if (NT == 2) {
                    int brow = wn * 16 + lr + (lt & 1) * 8 + t * DIL;
                    int bcol = kc * 16 + (lt >> 1) * 8;
                    ldsm4(bh, su32(xtH + brow * SB + bcol));
                    ldsm4(bl, su32(xtL + brow * SB + bcol));
                } else {
                    int brow = wn * 8 + lr + t * DIL;
                    int bcol = kc * 16 + ((ln >> 3) & 1) * 8;
                    ldsm2(bh, su32(xtH + brow * SB + bcol));
                    ldsm2(bl, su32(xtL + brow * SB + bcol));
                }
                #pragma unroll
                for (int nt = 0; nt < NT; nt++) {
                    unsigned bh0 = (NT == 2) ? bh[nt] : bh[0];
                    unsigned bh1 = (NT == 2) ? bh[nt + 2] : bh[1];
                    unsigned bl0 = (NT == 2) ? bl[nt] : bl[0];
                    unsigned bl1 = (NT == 2) ? bl[nt + 2] : bl[1];
                    #pragma unroll
                    for (int mt = 0; mt < 2; mt++) {
                        mma_bf16(acc[mt][nt], ah[mt], bh0, bh1);
                        mma_bf16(acc[mt][nt], ah[mt], bl0, bl1);
                        mma_bf16(acc[mt][nt], al[mt], bh0, bh1);
                    }
                }
            }

            if (t < 4) {
                if (!DBUF) __syncthreads();   // single buffer: wait for readers
                __nv_bfloat16* dH = waB + (DBUF ? ((t + 1) & 1) * WBUF : 0);
                __nv_bfloat16* dL = dH + NBUF * WBUF;
                #pragma unroll
                for (int j = 0; j < PW; j++) {
                    __nv_bfloat16 hv, lv; split_bf16(nxt[j], hv, lv);
                    dH[pco[j] * SB + pci[j]] = hv;
                    dL[pco[j] * SB + pci[j]] = lv;
                }
                __syncthreads();
            }
        }

        // ---- conv1 epilogue: bias + relu + split -> hT (l-major) ----
        __syncthreads();   // all mma done before hT overwrite (hT read last half)
        #pragma unroll
        for (int mt = 0; mt < 2; mt++) {
            int m = wm * 32 + mt * 16 + lg;
            float bb0 = b1s[coB + m], bb1 = b1s[coB + m + 8];
            #pragma unroll
            for (int nt = 0; nt < NT; nt++) {
                int n = ((NT == 2) ? wn * 16 + nt * 8 : wn * 8) + 2 * lq;
                float* a = acc[mt][nt];
                float v00 = a[0] + bb0, v01 = a[1] + bb0;
                float v10 = a[2] + bb1, v11 = a[3] + bb1;
                v00 = v00 > 0.f ? v00 : 0.f;  v01 = v01 > 0.f ? v01 : 0.f;
                v10 = v10 > 0.f ? v10 : 0.f;  v11 = v11 > 0.f ? v11 : 0.f;
                __nv_bfloat16 hv, lv;
                split_bf16(v00, hv, lv); hH[n * SH + m] = hv;           hL[n * SH + m] = lv;
                split_bf16(v01, hv, lv); hH[(n + 1) * SH + m] = hv;     hL[(n + 1) * SH + m] = lv;
                split_bf16(v10, hv, lv); hH[n * SH + m + 8] = hv;       hL[n * SH + m + 8] = lv;
                split_bf16(v11, hv, lv); hH[(n + 1) * SH + m + 8] = hv; hL[(n + 1) * SH + m + 8] = lv;
            }
        }
        __syncthreads();

        // ---- conv2 partial (k over this half's 64 channels) ----
        #pragma unroll
        for (int kc = 0; kc < 4; kc++) {
            unsigned ah[4], al[4];
            {
                int arow = wm2 * 16 + lr + (lt & 1) * 8;
                int acol = coB + kc * 16 + (lt >> 1) * 8;
                ldsm4(ah, su32(w2H + arow * S2 + acol));
                ldsm4(al, su32(w2L + arow * S2 + acol));
            }
            unsigned bh[4], bl[4];
            if (NT == 2) {
                int brow = wn2 * 16 + lr + (lt & 1) * 8;
                int bcol = kc * 16 + (lt >> 1) * 8;
                ldsm4(bh, su32(hH + brow * SH + bcol));
                ldsm4(bl, su32(hL + brow * SH + bcol));
            } else {
                int brow = wn2 * 8 + lr;
                int bcol = kc * 16 + ((ln >> 3) & 1) * 8;
                ldsm2(bh, su32(hH + brow * SH + bcol));
                ldsm2(bl, su32(hL + brow * SH + bcol));
            }
            #pragma unroll
            for (int nt = 0; nt < NT; nt++) {
                unsigned bh0 = (NT == 2) ? bh[nt] : bh[0];
                unsigned bh1 = (NT == 2) ? bh[nt + 2] : bh[1];
                unsigned bl0 = (NT == 2) ? bl[nt] : bl[0];
                unsigned bl1 = (NT == 2) ? bl[nt + 2] : bl[1];
                mma_bf16(a2[nt], ah, bh0, bh1);
                mma_bf16(a2[nt], ah, bl0, bl1);
                mma_bf16(a2[nt], al, bh0, bh1);
            }
        }
    }

    // ---- conv2 epilogue: bias + relu -> global ----
    float* yb = yout + (long)b * oss;
    {
        int row = wm2 * 16 + lg;
        float bb0 = b2s[row], bb1 = b2s[row + 8];
        #pragma unroll
        for (int nt = 0; nt < NT; nt++) {
            int col = ((NT == 2) ? wn2 * 16 + nt * 8 : wn2 * 8) + 2 * lq;
            float v0 = a2[nt][0] + bb0, v1 = a2[nt][1] + bb0;
            float v2 = a2[nt][2] + bb1, v3 = a2[nt][3] + bb1;
            v0 = v0 > 0.f ? v0 : 0.f;  v1 = v1 > 0.f ? v1 : 0.f;
            v2 = v2 > 0.f ? v2 : 0.f;  v3 = v3 > 0.f ? v3 : 0.f;
            *(float2*)&yb[(long)row * LLEN + l0 + col]       = make_float2(v0, v1);
            *(float2*)&yb[(long)(row + 8) * LLEN + l0 + col] = make_float2(v2, v3);
        }
    }
}

// ------------------------------------------------------------------
// compress conv (192 -> 64, 1x1) fused with avgpool(2)+repeat(2)
// ------------------------------------------------------------------
#define CTILE 64
__global__ void __launch_bounds__(512, 2)
comp_kernel(const float* __restrict__ cat, const float* __restrict__ cw,
            const float* __restrict__ cb, float* __restrict__ out)
{
    extern __shared__ float sm[];
    float* xs  = sm;
    float* ws  = xs + 192 * CTILE;
    float* cbs = ws + 192 * 64;

    const int b    = blockIdx.y;
    const int l0   = blockIdx.x * CTILE;
    const int tid  = threadIdx.x;
    const int warp = tid >> 5;
    const int ln   = tid & 31;
    const int wg   = warp >> 3;
    const int wc   = warp & 7;
    const int lb   = wg * 32 + ln;

    const float* catb = cat + (long)b * 192 * LLEN;
    for (int i = tid; i < 192 * CTILE; i += 512) {
        int ch = i / CTILE, j = i - ch * CTILE;
        xs[i] = catb[(long)ch * LLEN + l0 + j];
    }
    for (int i = tid; i < 64 * 192; i += 512) {
        int co = i & 63, k = i >> 6;
        ws[k * 64 + co] = cw[co * 192 + k];
    }
    if (tid < 64) cbs[tid] = cb[tid];
    __syncthreads();

    float acc[8];
    #pragma unroll
    for (int c = 0; c < 8; c++) acc[c] = 0.f;

    #pragma unroll 4
    for (int k = 0; k < 192; k++) {
        float4 wA = *(const float4*)(ws + k * 64 + wc * 8);
        float4 wB = *(const float4*)(ws + k * 64 + wc * 8 + 4);
        float xv = xs[k * CTILE + lb];
        acc[0] = fmaf(wA.x, xv, acc[0]);
        acc[1] = fmaf(wA.y, xv, acc[1]);
        acc[2] = fmaf(wA.z, xv, acc[2]);
        acc[3] = fmaf(wA.w, xv, acc[3]);
        acc[4] = fmaf(wB.x, xv, acc[4]);
        acc[5] = fmaf(wB.y, xv, acc[5]);
        acc[6] = fmaf(wB.z, xv, acc[6]);
        acc[7] = fmaf(wB.w, xv, acc[7]);
    }

    float* ob = out + (long)b * 64 * LLEN;
    #pragma unroll
    for (int c = 0; c < 8; c++) {
        int co = wc * 8 + c;
        float v = acc[c] + cbs[co];
        float p = __shfl_xor_sync(0xffffffffu, v, 1);
        ob[(long)co * LLEN + l0 + lb] = 0.5f * (v + p);
    }
}

// ------------------------------------------------------------------
// final per-sample 1x1 conv: 192 -> 1. Grid (4, NB), 256 thr.
// ------------------------------------------------------------------
__global__ void __launch_bounds__(256, 1)
final_kernel(const float* __restrict__ dec, const float* __restrict__ cw,
             const float* __restrict__ cbv, float* __restrict__ out)
{
    __shared__ float ws[192];
    const int b   = blockIdx.y;
    const int tid = threadIdx.x;
    const int l   = blockIdx.x * 256 + tid;
    const int c   = g_ids[b];
    if (tid < 192) ws[tid] = cw[(long)c * 192 + tid];
    __syncthreads();
    float s = cbv[c];
    const float* db = dec + (long)b * 192 * LLEN + l;
    #pragma unroll 8
    for (int ch = 0; ch < 192; ch++) s = fmaf(ws[ch], db[(long)ch * LLEN], s);
    out[(long)b * LLEN + l] = s;
}

// ------------------------------------------------------------------
static constexpr int smem_mma(int cin, int dil, int til) {
    int cinp = cin < 16 ? 16 : cin;
    int sb   = cinp + 8;
    int nbuf = (cin <= 32) ? 2 : 1;
    int xw   = til + 4 * dil;
    int elems = 2 * xw * sb + 2 * nbuf * 64 * sb + 2 * til * 72 + 2 * 32 * 136;
    return elems * 2 + 160 * 4;
}
static constexpr int SMEM_C = (192 * CTILE + 192 * 64 + 64) * 4;

template<int CIN, int DIL, int TIL>
static void launch_block(const float* xin, long iss, int ics,
                         const float* w1, const float* b1,
                         const float* w2, const float* b2,
                         float* yout, long oss,
                         const int* ids, long w1cs, long b1cs, long w2cs, long b2cs)
{
    static bool attr_done = false;
    if (!attr_done) {
        cudaFuncSetAttribute(block_mma_kernel<CIN, DIL, TIL>,
                             cudaFuncAttributeMaxDynamicSharedMemorySize,
                             smem_mma(CIN, DIL, TIL));
        attr_done = true;
    }
    dim3 grid(LLEN / TIL, NB);
    block_mma_kernel<CIN, DIL, TIL><<<grid, 512, smem_mma(CIN, DIL, TIL)>>>(
        xin, iss, ics, w1, b1, w2, b2, yout, oss, ids, w1cs, b1cs, w2cs, b2cs);
}

extern "C" void kernel_launch(void* const* d_in, const int* in_sizes, int n_in,
                              void* d_out, int out_size)
{
    const float* x        = (const float*)d_in[0];
    const float* enc0_w1  = (const float*)d_in[1];
    const float* enc0_b1  = (const float*)d_in[2];
    const float* enc0_w2  = (const float*)d_in[3];
    const float* enc0_b2  = (const float*)d_in[4];
    const float* enc_w1   = (const float*)d_in[5];
    const float* enc_b1   = (const float*)d_in[6];
    const float* enc_w2   = (const float*)d_in[7];
    const float* enc_b2   = (const float*)d_in[8];
    const float* comp_w   = (const float*)d_in[9];
    const float* comp_b   = (const float*)d_in[10];
    const float* decf0_w1 = (const float*)d_in[11];
    const float* decf0_b1 = (const float*)d_in[12];
    const float* decf0_w2 = (const float*)d_in[13];
    const float* decf0_b2 = (const float*)d_in[14];
    const float* decf_w1  = (const float*)d_in[15];
    const float* decf_b1  = (const float*)d_in[16];
    const float* decf_w2  = (const float*)d_in[17];
    const float* decf_b2  = (const float*)d_in[18];
    const float* decv_w1  = (const float*)d_in[19];
    const float* decv_b1  = (const float*)d_in[20];
    const float* decv_w2  = (const float*)d_in[21];
    const float* decv_b2  = (const float*)d_in[22];
    const float* decv_cw  = (const float*)d_in[23];
    const float* decv_cb  = (const float*)d_in[24];
    float* out = (float*)d_out;

    float *cat, *dec, *encU;
    int* idsp;
    cudaGetSymbolAddress((void**)&cat,  g_cat);
    cudaGetSymbolAddress((void**)&dec,  g_dec);
    cudaGetSymbolAddress((void**)&encU, g_encU);
    cudaGetSymbolAddress((void**)&idsp, g_ids);

    cudaFuncSetAttribute(comp_kernel, cudaFuncAttributeMaxDynamicSharedMemorySize, SMEM_C);

    const long SS = (long)192 * LLEN;

    ids_kernel<<<1, 64>>>(x);

    // ---- encoder ----
    launch_block<1, 1, 128>(x, (long)(LLEN + 1), 0,
                            enc0_w1, enc0_b1, enc0_w2, enc0_b2,
                            cat, SS, nullptr, 0, 0, 0, 0);
    launch_block<32, 2, 128>(cat + 0 * 32 * LLEN, SS, LLEN,
                             enc_w1 + 0 * 20480, enc_b1 + 0 * 128, enc_w2 + 0 * 4096, enc_b2 + 0 * 32,
                             cat + 1 * 32 * LLEN, SS, nullptr, 0, 0, 0, 0);
    launch_block<32, 4, 128>(cat + 1 * 32 * LLEN, SS, LLEN,
                             enc_w1 + 1 * 20480, enc_b1 + 1 * 128, enc_w2 + 1 * 4096, enc_b2 + 1 * 32,
                             cat + 2 * 32 * LLEN, SS, nullptr, 0, 0, 0, 0);
    launch_block<32, 8, 128>(cat + 2 * 32 * LLEN, SS, LLEN,
                             enc_w1 + 2 * 20480, enc_b1 + 2 * 128, enc_w2 + 2 * 4096, enc_b2 + 2 * 32,
                             cat + 3 * 32 * LLEN, SS, nullptr, 0, 0, 0, 0);
    launch_block<32, 16, 128>(cat + 3 * 32 * LLEN, SS, LLEN,
                              enc_w1 + 3 * 20480, enc_b1 + 3 * 128, enc_w2 + 3 * 4096, enc_b2 + 3 * 32,
                              cat + 4 * 32 * LLEN, SS, nullptr, 0, 0, 0, 0);
    launch_block<32, 32, 64>(cat + 4 * 32 * LLEN, SS, LLEN,
                             enc_w1 + 4 * 20480, enc_b1 + 4 * 128, enc_w2 + 4 * 4096, enc_b2 + 4 * 32,
                             cat + 5 * 32 * LLEN, SS, nullptr, 0, 0, 0, 0);

    // ---- compress + pool + upsample ----
    {
        dim3 grid(LLEN / CTILE, NB);
        comp_kernel<<<grid, 512, SMEM_C>>>(cat, comp_w, comp_b, encU);
    }

    // ---- fixed decoder ----
    launch_block<64, 32, 64>(encU, (long)64 * LLEN, LLEN,
                             decf0_w1, decf0_b1, decf0_w2, decf0_b2,
                             dec, SS, nullptr, 0, 0, 0, 0);
    launch_block<32, 16, 128>(dec + 0 * 32 * LLEN, SS, LLEN,
                              decf_w1 + 0 * 20480, decf_b1 + 0 * 128, decf_w2 + 0 * 4096, decf_b2 + 0 * 32,
                              dec + 1 * 32 * LLEN, SS, nullptr, 0, 0, 0, 0);
    launch_block<32, 8, 128>(dec + 1 * 32 * LLEN, SS, LLEN,
                             decf_w1 + 1 * 20480, decf_b1 + 1 * 128, decf_w2 + 1 * 4096, decf_b2 + 1 * 32,
                             dec + 2 * 32 * LLEN, SS, nullptr, 0, 0, 0, 0);
    launch_block<32, 4, 128>(dec + 2 * 32 * LLEN, SS, LLEN,
                             decf_w1 + 2 * 20480, decf_b1 + 2 * 128, decf_w2 + 2 * 4096, decf_b2 + 2 * 32,
                             dec + 3 * 32 * LLEN, SS, nullptr, 0, 0, 0, 0);

    // ---- variable decoder: per-sample selected combination ----
    launch_block<32, 2, 128>(dec + 3 * 32 * LLEN, SS, LLEN,
                             decv_w1 + 0 * 20480, decv_b1 + 0 * 128, decv_w2 + 0 * 4096, decv_b2 + 0 * 32,
                             dec + 4 * 32 * LLEN, SS,
                             idsp, 40960, 256, 8192, 64);
    launch_block<32, 1, 128>(dec + 4 * 32 * LLEN, SS, LLEN,
                             decv_w1 + 1 * 20480, decv_b1 + 1 * 128, decv_w2 + 1 * 4096, decv_b2 + 1 * 32,
                             dec + 5 * 32 * LLEN, SS,
                             idsp, 40960, 256, 8192, 64);

    // ---- final 1x1 conv (per-sample weights) ----
    {
        dim3 grid(4, NB);
        final_kernel<<<grid, 256>>>(dec, decv_cw, decv_cb, out);
    }
}